// round 1
// baseline (speedup 1.0000x reference)
#include <cuda_runtime.h>

// Spacial IRNN: 4 directional scans over [B,C,H,W] = [4,64,256,256] fp32.
// out[dir][b][c][h][w], dir: 0=up, 1=right, 2=down, 3=left.
// Recurrence: h_0 = x_edge (raw), h_t = relu(w_c * h_{t-1} + b_c + x_t).

#define HH 256
#define WW 256
#define BB 4
#define CC 64

constexpr int HW = HH * WW;
constexpr long long DIRSZ = (long long)BB * CC * HH * WW;  // 16,777,216 elements

// ---------------------------------------------------------------------------
// Vertical kernel: one thread per (b,c,w) column. Warp = 32 consecutive w ->
// all global loads/stores are coalesced 128B transactions.
// Forward pass -> down (dir 2), backward pass -> up (dir 0).
// ---------------------------------------------------------------------------
__global__ void vscan_kernel(const float* __restrict__ x,
                             const float* __restrict__ w_up,
                             const float* __restrict__ b_up,
                             const float* __restrict__ w_down,
                             const float* __restrict__ b_down,
                             float* __restrict__ out)
{
    int id = blockIdx.x * blockDim.x + threadIdx.x;  // 0 .. B*C*W-1
    int w  = id & (WW - 1);
    int bc = id >> 8;            // id / W
    int c  = bc & (CC - 1);      // bc % C

    const float* xp = x + (size_t)bc * HW + w;
    float* od = out + 2 * DIRSZ + (size_t)bc * HW + w;  // down
    float* ou = out + 0 * DIRSZ + (size_t)bc * HW + w;  // up

    float wd = w_down[c], bd = b_down[c];
    float wu = w_up[c],   bu = b_up[c];

    // down: forward over h
    float s = xp[0];
    od[0] = s;
#pragma unroll 8
    for (int h = 1; h < HH; ++h) {
        float xv = xp[h * WW];
        s = fmaxf(fmaf(wd, s, bd + xv), 0.0f);
        od[h * WW] = s;
    }

    // up: backward over h (input re-read served mostly from L2)
    s = xp[(HH - 1) * WW];
    ou[(HH - 1) * WW] = s;
#pragma unroll 8
    for (int h = HH - 2; h >= 0; --h) {
        float xv = xp[h * WW];
        s = fmaxf(fmaf(wu, s, bu + xv), 0.0f);
        ou[h * WW] = s;
    }
}

// ---------------------------------------------------------------------------
// Horizontal kernel: scan runs along contiguous w. Stage 128 rows x 32 cols
// in shared memory (stride 33 -> conflict-free in both access phases).
// Each thread owns one row; recurrence state carried in a register across
// the 8 chunks. Forward chunk order -> right (dir 1), backward -> left (dir 3).
// Since ROWS=128 divides H=256 and blocks are row-aligned, every block lies
// within a single (b,c) slab -> uniform channel params per block.
// ---------------------------------------------------------------------------
constexpr int ROWS   = 128;
constexpr int CHUNK  = 32;
constexpr int NCHUNK = WW / CHUNK;  // 8

__global__ void __launch_bounds__(ROWS)
hscan_kernel(const float* __restrict__ x,
             const float* __restrict__ w_right,
             const float* __restrict__ b_right,
             const float* __restrict__ w_left,
             const float* __restrict__ b_left,
             float* __restrict__ out)
{
    __shared__ float tile[ROWS][CHUNK + 1];

    const int tid = threadIdx.x;
    const int r0  = blockIdx.x * ROWS;        // first global row of this block
    const int bc  = r0 / HH;                  // uniform within block
    const int c   = bc & (CC - 1);

    const float* xbase = x + (size_t)r0 * WW;
    float* orr = out + 1 * DIRSZ + (size_t)r0 * WW;  // right
    float* ol  = out + 3 * DIRSZ + (size_t)r0 * WW;  // left

    const float wr = w_right[c], br = b_right[c];
    const float wl = w_left[c],  bl = b_left[c];

    // ---- right: forward over w ----
    {
        float s = 0.0f;
        for (int ch = 0; ch < NCHUNK; ++ch) {
            const int w0 = ch * CHUNK;
            __syncthreads();  // previous chunk's store phase done reading tile
#pragma unroll
            for (int k = 0; k < 32; ++k) {
                int lin = k * ROWS + tid;
                int row = lin >> 5;
                int col = lin & 31;
                tile[row][col] = xbase[(size_t)row * WW + w0 + col];
            }
            __syncthreads();
#pragma unroll
            for (int t = 0; t < CHUNK; ++t) {
                float xv = tile[tid][t];
                if (ch == 0 && t == 0) s = xv;
                else                   s = fmaxf(fmaf(wr, s, br + xv), 0.0f);
                tile[tid][t] = s;
            }
            __syncthreads();
#pragma unroll
            for (int k = 0; k < 32; ++k) {
                int lin = k * ROWS + tid;
                int row = lin >> 5;
                int col = lin & 31;
                orr[(size_t)row * WW + w0 + col] = tile[row][col];
            }
        }
    }

    // ---- left: backward over w (input re-read served mostly from L2) ----
    {
        float s = 0.0f;
        for (int ch = NCHUNK - 1; ch >= 0; --ch) {
            const int w0 = ch * CHUNK;
            __syncthreads();
#pragma unroll
            for (int k = 0; k < 32; ++k) {
                int lin = k * ROWS + tid;
                int row = lin >> 5;
                int col = lin & 31;
                tile[row][col] = xbase[(size_t)row * WW + w0 + col];
            }
            __syncthreads();
#pragma unroll
            for (int t = CHUNK - 1; t >= 0; --t) {
                float xv = tile[tid][t];
                if (ch == NCHUNK - 1 && t == CHUNK - 1) s = xv;
                else s = fmaxf(fmaf(wl, s, bl + xv), 0.0f);
                tile[tid][t] = s;
            }
            __syncthreads();
#pragma unroll
            for (int k = 0; k < 32; ++k) {
                int lin = k * ROWS + tid;
                int row = lin >> 5;
                int col = lin & 31;
                ol[(size_t)row * WW + w0 + col] = tile[row][col];
            }
        }
    }
}

// ---------------------------------------------------------------------------
// Launch
// ---------------------------------------------------------------------------
extern "C" void kernel_launch(void* const* d_in, const int* in_sizes, int n_in,
                              void* d_out, int out_size)
{
    const float* x       = (const float*)d_in[0];
    const float* w_up    = (const float*)d_in[1];
    const float* w_right = (const float*)d_in[2];
    const float* w_down  = (const float*)d_in[3];
    const float* w_left  = (const float*)d_in[4];
    const float* b_up    = (const float*)d_in[5];
    const float* b_right = (const float*)d_in[6];
    const float* b_down  = (const float*)d_in[7];
    const float* b_left  = (const float*)d_in[8];
    float* out = (float*)d_out;

    // Vertical: B*C*W = 65536 threads
    {
        int nthreads = BB * CC * WW;
        int tpb = 256;
        vscan_kernel<<<nthreads / tpb, tpb>>>(x, w_up, b_up, w_down, b_down, out);
    }
    // Horizontal: B*C*H = 65536 rows, 128 rows per block
    {
        int nrows = BB * CC * HH;
        hscan_kernel<<<nrows / ROWS, ROWS>>>(x, w_right, b_right, w_left, b_left, out);
    }
}

// round 2
// speedup vs baseline: 1.5511x; 1.5511x over previous
#include <cuda_runtime.h>

// Spacial IRNN: 4 directional relu-scans over [B,C,H,W] = [4,64,256,256] fp32.
// out[dir][b][c][h][w], dir: 0=up, 1=right, 2=down, 3=left.
// h_0 = x_edge (raw), h_t = relu(w_c * h_{t-1} + b_c + x_t).
//
// Single fused kernel. role = blockIdx.x % 3:
//   role 0          -> vertical block (up+down, interleaved chains, ILP=2)
//   role 1,2        -> horizontal block (128 rows; threads 0-127 scan right,
//                      threads 128-255 scan left on a second tile)

#define HH 256
#define WW 256
#define BB 4
#define CC 64

constexpr int HW = HH * WW;
constexpr long long DIRSZ = (long long)BB * CC * HH * WW;  // 16,777,216

constexpr int TPB     = 256;
constexpr int VBLOCKS = (BB * CC * WW) / TPB;   // 256
constexpr int HROWS   = 128;
constexpr int HBLOCKS = (BB * CC * HH) / HROWS; // 512
constexpr int CHUNK   = 32;
constexpr int NCHUNK  = WW / CHUNK;             // 8

__global__ void __launch_bounds__(TPB, 5)
irnn_fused_kernel(const float* __restrict__ x,
                  const float* __restrict__ w_up,    const float* __restrict__ b_up,
                  const float* __restrict__ w_right, const float* __restrict__ b_right,
                  const float* __restrict__ w_down,  const float* __restrict__ b_down,
                  const float* __restrict__ w_left,  const float* __restrict__ b_left,
                  float* __restrict__ out)
{
    __shared__ float tA[HROWS][CHUNK + 1];   // right-direction staging
    __shared__ float tB[HROWS][CHUNK + 1];   // left-direction staging

    const int role = blockIdx.x % 3;
    const int grp  = blockIdx.x / 3;
    const int tid  = threadIdx.x;

    if (role == 0) {
        // ------------------- vertical: one thread per (b,c,w) column --------
        int id = grp * TPB + tid;            // 0 .. B*C*W-1
        int w  = id & (WW - 1);
        int bc = id >> 8;
        int c  = bc & (CC - 1);

        const float* xp = x + (size_t)bc * HW + w;
        float* od = out + 2 * DIRSZ + (size_t)bc * HW + w;  // down
        float* ou = out + 0 * DIRSZ + (size_t)bc * HW + w;  // up

        const float wd = w_down[c], bd = b_down[c];
        const float wu = w_up[c],   bu = b_up[c];

        float sd = xp[0];                 od[0] = sd;
        float su = xp[(HH - 1) * WW];     ou[(HH - 1) * WW] = su;

#pragma unroll 8
        for (int h = 1; h < HH; ++h) {
            float xd = xp[h * WW];
            float xu = xp[(HH - 1 - h) * WW];
            sd = fmaxf(fmaf(wd, sd, bd + xd), 0.0f);
            su = fmaxf(fmaf(wu, su, bu + xu), 0.0f);
            od[h * WW] = sd;
            ou[(HH - 1 - h) * WW] = su;
        }
    } else {
        // ------------------- horizontal: 128 rows, both directions ----------
        const int hb = grp * 2 + (role - 1);     // 0 .. 511
        const int r0 = hb * HROWS;               // first global row
        const int bc = r0 >> 8;                  // uniform within block
        const int c  = bc & (CC - 1);

        const float* xbase = x + (size_t)r0 * WW;
        float* orr = out + 1 * DIRSZ + (size_t)r0 * WW;  // right
        float* ol  = out + 3 * DIRSZ + (size_t)r0 * WW;  // left

        const bool isLeft = (tid >= HROWS);
        const int  r      = tid & (HROWS - 1);           // owned row

        const float wsc = isLeft ? w_left[c] : w_right[c];
        const float bsc = isLeft ? b_left[c] : b_right[c];

        // staging map: affine in k -> low register pressure, fully coalesced
        const int colL = tid & (CHUNK - 1);
        const int rowB = tid >> 5;                       // 0..7

        float s = 0.0f;
        for (int ch = 0; ch < NCHUNK; ++ch) {
            const int wA = ch * CHUNK;                   // right chunk (fwd)
            const int wB = (NCHUNK - 1 - ch) * CHUNK;    // left  chunk (bwd)

            // load both tiles cooperatively (coalesced 128B lines)
#pragma unroll
            for (int k = 0; k < 16; ++k) {
                int row = rowB + k * 8;
                tA[row][colL] = xbase[(size_t)row * WW + wA + colL];
                tB[row][colL] = xbase[(size_t)row * WW + wB + colL];
            }
            __syncthreads();

            // scan owned row in smem (stride 33 -> conflict-free)
            if (!isLeft) {
#pragma unroll
                for (int t = 0; t < CHUNK; ++t) {
                    float xv = tA[r][t];
                    if (ch == 0 && t == 0) s = xv;
                    else s = fmaxf(fmaf(wsc, s, bsc + xv), 0.0f);
                    tA[r][t] = s;
                }
            } else {
#pragma unroll
                for (int t = CHUNK - 1; t >= 0; --t) {
                    float xv = tB[r][t];
                    if (ch == 0 && t == CHUNK - 1) s = xv;
                    else s = fmaxf(fmaf(wsc, s, bsc + xv), 0.0f);
                    tB[r][t] = s;
                }
            }
            __syncthreads();

            // store both tiles (coalesced)
#pragma unroll
            for (int k = 0; k < 16; ++k) {
                int row = rowB + k * 8;
                orr[(size_t)row * WW + wA + colL] = tA[row][colL];
                ol [(size_t)row * WW + wB + colL] = tB[row][colL];
            }
            __syncthreads();
        }
    }
}

extern "C" void kernel_launch(void* const* d_in, const int* in_sizes, int n_in,
                              void* d_out, int out_size)
{
    const float* x       = (const float*)d_in[0];
    const float* w_up    = (const float*)d_in[1];
    const float* w_right = (const float*)d_in[2];
    const float* w_down  = (const float*)d_in[3];
    const float* w_left  = (const float*)d_in[4];
    const float* b_up    = (const float*)d_in[5];
    const float* b_right = (const float*)d_in[6];
    const float* b_down  = (const float*)d_in[7];
    const float* b_left  = (const float*)d_in[8];
    float* out = (float*)d_out;

    int grid = VBLOCKS + HBLOCKS;   // 256 vertical + 512 horizontal = 768
    irnn_fused_kernel<<<grid, TPB>>>(x,
                                     w_up, b_up, w_right, b_right,
                                     w_down, b_down, w_left, b_left,
                                     out);
}

// round 3
// speedup vs baseline: 1.5580x; 1.0044x over previous
#include <cuda_runtime.h>

// Spacial IRNN: 4 directional relu-scans over [B,C,H,W] = [4,64,256,256] fp32.
// out[dir][b][c][h][w], dir: 0=up, 1=right, 2=down, 3=left.
// h_0 = x_edge (raw), h_t = relu(w_c * h_{t-1} + b_c + x_t).
//
// Fused kernel, role = blockIdx.x % 9:
//   role 0    -> vertical block: one thread per 4 columns (float4), up+down
//                interleaved -> 8 independent chains per thread.
//   role 1..8 -> horizontal block: 128 rows staged in smem, threads 0-127 scan
//                right, 128-255 scan left; global I/O via float4.

#define HH 256
#define WW 256
#define BB 4
#define CC 64

constexpr int HW = HH * WW;
constexpr long long DIRSZ = (long long)BB * CC * HH * WW;  // 16,777,216

constexpr int TPB     = 256;
constexpr int VBLOCKS = (BB * CC * WW / 4) / TPB;   // 64   (16384 f4-threads)
constexpr int HROWS   = 128;
constexpr int HBLOCKS = (BB * CC * HH) / HROWS;     // 512
constexpr int CHUNK   = 32;
constexpr int NCHUNK  = WW / CHUNK;                 // 8
constexpr int TSTRIDE = CHUNK + 1;                  // 33, conflict-free scan

__device__ __forceinline__ float4 step4(float w, float4 s, float b, float4 x) {
    float4 r;
    r.x = fmaxf(fmaf(w, s.x, b + x.x), 0.0f);
    r.y = fmaxf(fmaf(w, s.y, b + x.y), 0.0f);
    r.z = fmaxf(fmaf(w, s.z, b + x.z), 0.0f);
    r.w = fmaxf(fmaf(w, s.w, b + x.w), 0.0f);
    return r;
}

__global__ void __launch_bounds__(TPB, 4)
irnn_fused_kernel(const float* __restrict__ x,
                  const float* __restrict__ w_up,    const float* __restrict__ b_up,
                  const float* __restrict__ w_right, const float* __restrict__ b_right,
                  const float* __restrict__ w_down,  const float* __restrict__ b_down,
                  const float* __restrict__ w_left,  const float* __restrict__ b_left,
                  float* __restrict__ out)
{
    __shared__ float tA[HROWS * TSTRIDE];   // right staging
    __shared__ float tB[HROWS * TSTRIDE];   // left  staging

    const int role = blockIdx.x % 9;
    const int grp  = blockIdx.x / 9;
    const int tid  = threadIdx.x;

    if (role == 0) {
        // ---------------- vertical: one thread per (b,c, 4w) ----------------
        const int id = grp * TPB + tid;        // 0 .. 16383
        const int w4 = id & 63;                // W/4 = 64
        const int bc = id >> 6;
        const int c  = bc & (CC - 1);
        const int RS = WW / 4;                 // 64 float4 per row

        const float4* xp = ((const float4*)(x + (size_t)bc * HW)) + w4;
        float4* od = ((float4*)(out + 2 * DIRSZ + (size_t)bc * HW)) + w4;  // down
        float4* ou = ((float4*)(out + 0 * DIRSZ + (size_t)bc * HW)) + w4;  // up

        const float wd = w_down[c], bd = b_down[c];
        const float wu = w_up[c],   bu = b_up[c];

        float4 sd = xp[0];
        float4 su = xp[(HH - 1) * RS];
        __stcs(&od[0], sd);
        __stcs(&ou[(HH - 1) * RS], su);

#pragma unroll 4
        for (int h = 1; h < HH; ++h) {
            float4 xd = xp[h * RS];
            float4 xu = xp[(HH - 1 - h) * RS];
            sd = step4(wd, sd, bd, xd);
            su = step4(wu, su, bu, xu);
            __stcs(&od[h * RS], sd);
            __stcs(&ou[(HH - 1 - h) * RS], su);
        }
    } else {
        // ---------------- horizontal: 128 rows, both directions -------------
        const int hb = grp * 8 + (role - 1);   // 0 .. 511
        const int r0 = hb * HROWS;
        const int bc = r0 >> 8;                // uniform within block
        const int c  = bc & (CC - 1);

        const float* xbase = x + (size_t)r0 * WW;
        float* orr = out + 1 * DIRSZ + (size_t)r0 * WW;  // right
        float* ol  = out + 3 * DIRSZ + (size_t)r0 * WW;  // left

        const bool isLeft = (tid >= HROWS);
        const int  r      = tid & (HROWS - 1);

        const float wsc = isLeft ? w_left[c] : w_right[c];
        const float bsc = isLeft ? b_left[c] : b_right[c];

        float s = 0.0f;
        for (int ch = 0; ch < NCHUNK; ++ch) {
            const int wA = ch * CHUNK;                 // right chunk (fwd)
            const int wB = (NCHUNK - 1 - ch) * CHUNK;  // left  chunk (bwd)

            // ---- load: LDG.128, scatter scalars into stride-33 tiles ------
            // f4 index f = k*256 + tid ; row = f>>3 ; col4 = f&7
#pragma unroll
            for (int k = 0; k < 4; ++k) {
                int f    = k * TPB + tid;
                int row  = f >> 3;
                int col4 = f & 7;
                float4 va = *(const float4*)&xbase[(size_t)row * WW + wA + col4 * 4];
                float4 vb = *(const float4*)&xbase[(size_t)row * WW + wB + col4 * 4];
                float* pa = &tA[row * TSTRIDE + col4 * 4];
                float* pb = &tB[row * TSTRIDE + col4 * 4];
                pa[0] = va.x; pa[1] = va.y; pa[2] = va.z; pa[3] = va.w;
                pb[0] = vb.x; pb[1] = vb.y; pb[2] = vb.z; pb[3] = vb.w;
            }
            __syncthreads();

            // ---- scan owned row in smem --------------------------------
            if (!isLeft) {
                float* tr = &tA[r * TSTRIDE];
#pragma unroll
                for (int t = 0; t < CHUNK; ++t) {
                    float xv = tr[t];
                    if (ch == 0 && t == 0) s = xv;
                    else s = fmaxf(fmaf(wsc, s, bsc + xv), 0.0f);
                    tr[t] = s;
                }
            } else {
                float* tr = &tB[r * TSTRIDE];
#pragma unroll
                for (int t = CHUNK - 1; t >= 0; --t) {
                    float xv = tr[t];
                    if (ch == 0 && t == CHUNK - 1) s = xv;
                    else s = fmaxf(fmaf(wsc, s, bsc + xv), 0.0f);
                    tr[t] = s;
                }
            }
            __syncthreads();

            // ---- store: gather scalars, STG.128 streaming -----------------
#pragma unroll
            for (int k = 0; k < 4; ++k) {
                int f    = k * TPB + tid;
                int row  = f >> 3;
                int col4 = f & 7;
                const float* pa = &tA[row * TSTRIDE + col4 * 4];
                const float* pb = &tB[row * TSTRIDE + col4 * 4];
                float4 va = make_float4(pa[0], pa[1], pa[2], pa[3]);
                float4 vb = make_float4(pb[0], pb[1], pb[2], pb[3]);
                __stcs((float4*)&orr[(size_t)row * WW + wA + col4 * 4], va);
                __stcs((float4*)&ol [(size_t)row * WW + wB + col4 * 4], vb);
            }
            __syncthreads();
        }
    }
}

extern "C" void kernel_launch(void* const* d_in, const int* in_sizes, int n_in,
                              void* d_out, int out_size)
{
    const float* x       = (const float*)d_in[0];
    const float* w_up    = (const float*)d_in[1];
    const float* w_right = (const float*)d_in[2];
    const float* w_down  = (const float*)d_in[3];
    const float* w_left  = (const float*)d_in[4];
    const float* b_up    = (const float*)d_in[5];
    const float* b_right = (const float*)d_in[6];
    const float* b_down  = (const float*)d_in[7];
    const float* b_left  = (const float*)d_in[8];
    float* out = (float*)d_out;

    int grid = VBLOCKS + HBLOCKS;   // 64 vertical + 512 horizontal = 576 (64*9)
    irnn_fused_kernel<<<grid, TPB>>>(x,
                                     w_up, b_up, w_right, b_right,
                                     w_down, b_down, w_left, b_left,
                                     out);
}